// round 8
// baseline (speedup 1.0000x reference)
#include <cuda_runtime.h>
#include <math.h>

#define B    64
#define T    4096
#define DIM  256
#define NLOC 32
#define KS   31
#define PAD  15
#define TPW  32             // rows per warp
#define WPB  8              // warps per block
#define TPB  (TPW * WPB)    // 256 t per block
#define NCH  (T / TPB)      // 16 chunks per batch -> 1024 blocks
#define NPAIR (TPW / 2)     // 16 row-pairs per warp

// -------- scratch (static device globals; no allocation allowed) ----------
__device__ float g_u[B * DIM];            // W^T q per batch
__device__ float g_g[B * KS];             // collapsed conv kernel per batch
__device__ float g_cb[B];                 // collapsed conv bias per batch
__device__ float g_energ[B * T];          // raw energies
__device__ float g_pm[B * NCH];           // per-block running max
__device__ float g_ps[B * NCH];           // per-block exp-sum
__device__ float g_pctx[B * NCH * DIM];   // per-block unnormalized context

// ---------------------------------------------------------------------------
// Kernel A: prep, parallelized. grid = (B, 9).
// ---------------------------------------------------------------------------
__global__ void __launch_bounds__(256)
prep_kernel(const float* __restrict__ q,
            const float* __restrict__ Ww,
            const float* __restrict__ Lw,
            const float* __restrict__ convw,
            const float* __restrict__ convb) {
    __shared__ float sq[DIM];
    __shared__ float part[8][32];
    __shared__ float sv[NLOC];

    const int b   = blockIdx.x;
    const int c   = blockIdx.y;
    const int tid = threadIdx.x;
    const int ln  = tid & 31;
    const int eg  = tid >> 5;

    sq[tid] = q[b * DIM + tid];
    __syncthreads();

    if (c < 8) {
        const float* wp = Ww + (size_t)(eg * 32) * DIM + c * 32 + ln;
        float acc = 0.f;
#pragma unroll
        for (int e = 0; e < 32; e++)
            acc = fmaf(wp[(size_t)e * DIM], sq[eg * 32 + e], acc);
        part[eg][ln] = acc;
        __syncthreads();
        if (tid < 32) {
            float u = part[0][tid];
#pragma unroll
            for (int j = 1; j < 8; j++) u += part[j][tid];
            g_u[b * DIM + c * 32 + tid] = u;
        }
    } else {
        const float* lp = Lw + (size_t)(eg * 32) * NLOC + ln;
        float acc = 0.f;
#pragma unroll
        for (int e = 0; e < 32; e++)
            acc = fmaf(lp[(size_t)e * NLOC], sq[eg * 32 + e], acc);
        part[eg][ln] = acc;
        __syncthreads();
        if (tid < 32) {
            float v = part[0][tid];
#pragma unroll
            for (int j = 1; j < 8; j++) v += part[j][tid];
            sv[tid] = v;
        }
        __syncthreads();
        if (tid < KS) {
            float gg = 0.f;
#pragma unroll
            for (int cc = 0; cc < NLOC; cc++)
                gg = fmaf(convw[cc * KS + tid], sv[cc], gg);
            g_g[b * KS + tid] = gg;
        }
        if (tid == 0) {
            float cb = 0.f;
#pragma unroll
            for (int cc = 0; cc < NLOC; cc++) cb = fmaf(convb[cc], sv[cc], cb);
            g_cb[b] = cb;
        }
    }
}

// ---------------------------------------------------------------------------
// Kernel B: HBM-bound pass. Row-pair processing, contiguous lane mapping
// (lane l owns dims [4l,4l+4) and [128+4l,128+4l+4)), prefetch depth = 2
// pairs -> 8 LDG.128 in flight per warp. PDL overlaps prep.
// ---------------------------------------------------------------------------
__global__ void __launch_bounds__(256, 3)
energy_ctx_kernel(const float* __restrict__ enc,
                  const float* __restrict__ mask) {
    __shared__ float smask[TPB + 2 * PAD];
    __shared__ float red_m[WPB], red_s[WPB];
    __shared__ __align__(16) float red_ctx[WPB][DIM];

    const int b   = blockIdx.x;
    const int ch  = blockIdx.y;
    const int tid = threadIdx.x;
    const int w   = tid >> 5;
    const int l   = tid & 31;
    const int t0  = ch * TPB;

    // ---- phase 1: independent of prep outputs ----
    for (int j = tid; j < TPB + 2 * PAD; j += 256) {
        int gt = t0 - PAD + j;
        smask[j] = (gt >= 0 && gt < T) ? mask[b * T + gt] : 0.f;
    }

    const int tw0 = t0 + w * TPW;
    const float* base = enc + ((size_t)tw0 * B + b) * DIM;
    const size_t stride = (size_t)B * DIM;
    const float* lp0 = base + 4 * l;        // dims [4l, 4l+4)
    const float* lp1 = base + 128 + 4 * l;  // dims [128+4l, ...)

    // prefetch pairs 0 and 1 (rows 0..3)
    float4 A0[2], A1[2], B0[2], B1[2];
    A0[0] = *(const float4*)(lp0);
    A1[0] = *(const float4*)(lp1);
    B0[0] = *(const float4*)(lp0 + stride);
    B1[0] = *(const float4*)(lp1 + stride);
    A0[1] = *(const float4*)(lp0 + 2 * stride);
    A1[1] = *(const float4*)(lp1 + 2 * stride);
    B0[1] = *(const float4*)(lp0 + 3 * stride);
    B1[1] = *(const float4*)(lp1 + 3 * stride);

    // ---- wait for prep (PDL) ----
    cudaGridDependencySynchronize();

    const float4 uA = *(const float4*)(g_u + b * DIM + 4 * l);
    const float4 uB = *(const float4*)(g_u + b * DIM + 128 + 4 * l);
    const float  gl = (l < KS) ? g_g[b * KS + l] : 0.f;
    const float  cb = g_cb[b];
    __syncthreads();   // smask ready

    float m = -INFINITY, s = 0.f;
    float cx[8] = {0.f, 0.f, 0.f, 0.f, 0.f, 0.f, 0.f, 0.f};

#pragma unroll 2
    for (int ip = 0; ip < NPAIR; ip++) {
        const int slot = ip & 1;
        const float4 a0 = A0[slot], a1 = A1[slot];
        const float4 b0 = B0[slot], b1 = B1[slot];
        if (ip + 2 < NPAIR) {
            const float* np0 = lp0 + (size_t)(2 * ip + 4) * stride;
            const float* np1 = lp1 + (size_t)(2 * ip + 4) * stride;
            A0[slot] = *(const float4*)(np0);
            A1[slot] = *(const float4*)(np1);
            B0[slot] = *(const float4*)(np0 + stride);
            B1[slot] = *(const float4*)(np1 + stride);
        }
        const float msk0 = (l < KS) ? smask[w * TPW + 2 * ip + l]     : 0.f;
        const float msk1 = (l < KS) ? smask[w * TPW + 2 * ip + 1 + l] : 0.f;

        float p0, p1;
        p0 = a0.x * uA.x;                 p1 = b0.x * uA.x;
        p0 = fmaf(a0.y, uA.y, p0);        p1 = fmaf(b0.y, uA.y, p1);
        p0 = fmaf(a0.z, uA.z, p0);        p1 = fmaf(b0.z, uA.z, p1);
        p0 = fmaf(a0.w, uA.w, p0);        p1 = fmaf(b0.w, uA.w, p1);
        p0 = fmaf(a1.x, uB.x, p0);        p1 = fmaf(b1.x, uB.x, p1);
        p0 = fmaf(a1.y, uB.y, p0);        p1 = fmaf(b1.y, uB.y, p1);
        p0 = fmaf(a1.z, uB.z, p0);        p1 = fmaf(b1.z, uB.z, p1);
        p0 = fmaf(a1.w, uB.w, p0);        p1 = fmaf(b1.w, uB.w, p1);
        p0 = fmaf(gl, msk0, p0);          p1 = fmaf(gl, msk1, p1);

#pragma unroll
        for (int off = 16; off > 0; off >>= 1) {   // two chains interleaved
            p0 += __shfl_xor_sync(0xffffffffu, p0, off);
            p1 += __shfl_xor_sync(0xffffffffu, p1, off);
        }
        p0 += cb; p1 += cb;

        if (l == 0) {
            float2 e2; e2.x = p0; e2.y = p1;
            *(float2*)(g_energ + b * T + tw0 + 2 * ip) = e2;
        }

        const float mp = fmaxf(p0, p1);
        if (mp > m) {                               // warp-uniform branch
            const float sc = __expf(m - mp);        // exp(-inf)=0 first time
            const float e0 = __expf(p0 - mp);
            const float e1 = __expf(p1 - mp);
            s = s * sc + e0 + e1;
            cx[0] = fmaf(cx[0], sc, fmaf(e0, a0.x, e1 * b0.x));
            cx[1] = fmaf(cx[1], sc, fmaf(e0, a0.y, e1 * b0.y));
            cx[2] = fmaf(cx[2], sc, fmaf(e0, a0.z, e1 * b0.z));
            cx[3] = fmaf(cx[3], sc, fmaf(e0, a0.w, e1 * b0.w));
            cx[4] = fmaf(cx[4], sc, fmaf(e0, a1.x, e1 * b1.x));
            cx[5] = fmaf(cx[5], sc, fmaf(e0, a1.y, e1 * b1.y));
            cx[6] = fmaf(cx[6], sc, fmaf(e0, a1.z, e1 * b1.z));
            cx[7] = fmaf(cx[7], sc, fmaf(e0, a1.w, e1 * b1.w));
            m = mp;
        } else {
            const float e0 = __expf(p0 - m);
            const float e1 = __expf(p1 - m);
            s += e0 + e1;
            cx[0] += fmaf(e0, a0.x, e1 * b0.x);
            cx[1] += fmaf(e0, a0.y, e1 * b0.y);
            cx[2] += fmaf(e0, a0.z, e1 * b0.z);
            cx[3] += fmaf(e0, a0.w, e1 * b0.w);
            cx[4] += fmaf(e0, a1.x, e1 * b1.x);
            cx[5] += fmaf(e0, a1.y, e1 * b1.y);
            cx[6] += fmaf(e0, a1.z, e1 * b1.z);
            cx[7] += fmaf(e0, a1.w, e1 * b1.w);
        }
    }

    // ---- block epilogue: merge 8 warp partials ----
    if (l == 0) { red_m[w] = m; red_s[w] = s; }
    *(float4*)(&red_ctx[w][4 * l])       = *(float4*)(&cx[0]);
    *(float4*)(&red_ctx[w][128 + 4 * l]) = *(float4*)(&cx[4]);
    __syncthreads();

    float M = red_m[0];
#pragma unroll
    for (int j = 1; j < WPB; j++) M = fmaxf(M, red_m[j]);
    float S = 0.f, C = 0.f;
#pragma unroll
    for (int j = 0; j < WPB; j++) {
        const float wj = __expf(red_m[j] - M);
        S = fmaf(red_s[j], wj, S);
        C = fmaf(wj, red_ctx[j][tid], C);
    }

    const int pidx = b * NCH + ch;
    g_pctx[pidx * DIM + tid] = C;
    if (tid == 0) { g_pm[pidx] = M; g_ps[pidx] = S; }
}

// ---------------------------------------------------------------------------
// Kernel C: per-batch combine + context + attn quarter. grid (B, 4).
// PDL: blocks launch early, sync before touching main-kernel outputs.
// ---------------------------------------------------------------------------
__global__ void __launch_bounds__(256)
finish_kernel(float* __restrict__ out) {
    __shared__ float sm[NCH], ss[NCH];
    const int b = blockIdx.x, sl = blockIdx.y, tid = threadIdx.x;

    cudaGridDependencySynchronize();

    if (tid < NCH) { sm[tid] = g_pm[b * NCH + tid]; ss[tid] = g_ps[b * NCH + tid]; }
    __syncthreads();

    float M = sm[0];
#pragma unroll
    for (int j = 1; j < NCH; j++) M = fmaxf(M, sm[j]);
    float S = 0.f;
#pragma unroll
    for (int j = 0; j < NCH; j++) S = fmaf(ss[j], __expf(sm[j] - M), S);
    const float invS = 1.0f / S;

    if (sl == 0) {
        float ctx = 0.f;
#pragma unroll
        for (int j = 0; j < NCH; j++)
            ctx = fmaf(__expf(sm[j] - M), g_pctx[(b * NCH + j) * DIM + tid], ctx);
        out[b * DIM + tid] = ctx * invS;
    }

    const float4* ep = (const float4*)(g_energ + (size_t)b * T) + sl * 256;
    float4*       op = (float4*)(out + (size_t)B * DIM + (size_t)b * T) + sl * 256;
    float4 e = ep[tid];
    float4 r;
    r.x = __expf(e.x - M) * invS;
    r.y = __expf(e.y - M) * invS;
    r.z = __expf(e.z - M) * invS;
    r.w = __expf(e.w - M) * invS;
    op[tid] = r;
}

// ---------------------------------------------------------------------------
extern "C" void kernel_launch(void* const* d_in, const int* in_sizes, int n_in,
                              void* d_out, int out_size) {
    const float* q     = (const float*)d_in[0];
    const float* enc   = (const float*)d_in[1];
    const float* mask  = (const float*)d_in[2];
    const float* Ww    = (const float*)d_in[3];
    const float* Lw    = (const float*)d_in[4];
    const float* convw = (const float*)d_in[5];
    const float* convb = (const float*)d_in[6];
    float* out = (float*)d_out;                  // context(16384) ++ attn(262144)

    dim3 gridA(B, 9);
    prep_kernel<<<gridA, 256>>>(q, Ww, Lw, convw, convb);

    cudaLaunchAttribute attrs[1];
    attrs[0].id = cudaLaunchAttributeProgrammaticStreamSerialization;
    attrs[0].val.programmaticStreamSerializationAllowed = 1;

    cudaLaunchConfig_t cfgB = {};
    cfgB.gridDim  = dim3(B, NCH);
    cfgB.blockDim = dim3(256);
    cfgB.attrs = attrs;
    cfgB.numAttrs = 1;
    cudaLaunchKernelEx(&cfgB, energy_ctx_kernel, enc, mask);

    cudaLaunchConfig_t cfgC = {};
    cfgC.gridDim  = dim3(B, 4);
    cfgC.blockDim = dim3(256);
    cfgC.attrs = attrs;
    cfgC.numAttrs = 1;
    cudaLaunchKernelEx(&cfgC, finish_kernel, out);
}